// round 6
// baseline (speedup 1.0000x reference)
#include <cuda_runtime.h>
#include <cstdint>

// Problem constants
constexpr int B = 4, S = 1024, D = 1024, H = 16, KH = 4, HD = 64;
constexpr int E = 8, HID = 2816;
constexpr int T = B * S;               // 4096 tokens
constexpr int NREP = H / KH;           // 4

// ---------------- scratch (device globals; no allocation allowed) -------------
__device__ float g_xn[(size_t)T * D];
__device__ float g_q [(size_t)T * H * HD];
__device__ float g_k [(size_t)T * KH * HD];
__device__ float g_v [(size_t)T * KH * HD];
__device__ float g_at[(size_t)T * H * HD];
__device__ float g_h [(size_t)T * D];
__device__ float g_hn[(size_t)T * D];
__device__ float g_act1[(size_t)E * T * HID];
__device__ float g_act [(size_t)E * T * HID];
__device__ float g_buf [(size_t)E * T * D];
__device__ int   g_cnt[E];
__device__ int   g_tok[E * T];
__device__ float g_wt [E * T];
__device__ int   g_slot[2 * T];

// ---------------- mma / cp.async helpers ----------------
__device__ __forceinline__ uint32_t f2tf32(float f) {
    uint32_t r;
    asm("cvt.rna.tf32.f32 %0, %1;" : "=r"(r) : "f"(f));
    return r;
}
__device__ __forceinline__ void mma_tf32(float d[4], const uint32_t a[4], const uint32_t b[2]) {
    asm volatile(
        "mma.sync.aligned.m16n8k8.row.col.f32.tf32.tf32.f32 "
        "{%0,%1,%2,%3},{%4,%5,%6,%7},{%8,%9},{%0,%1,%2,%3};\n"
        : "+f"(d[0]), "+f"(d[1]), "+f"(d[2]), "+f"(d[3])
        : "r"(a[0]), "r"(a[1]), "r"(a[2]), "r"(a[3]), "r"(b[0]), "r"(b[1]));
}
__device__ __forceinline__ void cp16(void* dst, const void* src, bool ok) {
    uint32_t d = (uint32_t)__cvta_generic_to_shared(dst);
    int sz = ok ? 16 : 0;
    asm volatile("cp.async.ca.shared.global [%0], [%1], 16, %2;\n"
                 :: "r"(d), "l"(src), "r"(sz));
}
__device__ __forceinline__ void cp_commit() { asm volatile("cp.async.commit_group;\n"); }
template<int N> __device__ __forceinline__ void cp_wait() {
    asm volatile("cp.async.wait_group %0;\n" :: "n"(N));
}

// ---------------- RMSNorm ----------------
__global__ __launch_bounds__(256) void rmsnorm_kernel(const float* __restrict__ x,
        const float* __restrict__ w, float* __restrict__ out) {
    int row = blockIdx.x;
    const float* xr = x + (size_t)row * D;
    float s = 0.f;
    for (int i = threadIdx.x; i < D; i += 256) { float v = xr[i]; s += v * v; }
    __shared__ float red[256];
    red[threadIdx.x] = s;
    __syncthreads();
    for (int o = 128; o > 0; o >>= 1) {
        if (threadIdx.x < o) red[threadIdx.x] += red[threadIdx.x + o];
        __syncthreads();
    }
    float inv = rsqrtf(red[0] / (float)D + 1e-5f);
    float* orow = out + (size_t)row * D;
    for (int i = threadIdx.x; i < D; i += 256) orow[i] = xr[i] * inv * w[i];
}

// ============ tf32 GEMM core: 128x128 tile, BK=16, 3-stage cp.async, 1 sync ===
// modes: 0 plain, 1 +add, 3 silu(aux)*acc. Optional expert batching + row gather.
__global__ __launch_bounds__(256, 2) void gemm_tf32(
        const float* __restrict__ A, const float* __restrict__ Bw,
        float* __restrict__ C,
        const float* __restrict__ add, const float* __restrict__ aux,
        const int* __restrict__ gtok, const int* __restrict__ gcnt,
        int M, int N, int K, int mode,
        long long strideAz, long long strideBz, long long strideCz) {
    int z = blockIdx.z;
    const float* Az = A + (size_t)z * strideAz;
    const float* Bz = Bw + (size_t)z * strideBz;
    float* Cz = C + (size_t)z * strideCz;
    const float* auxz = aux ? aux + (size_t)z * strideCz : nullptr;

    int c = gcnt ? gcnt[z] : M;
    int bm = blockIdx.y * 128;
    if (bm >= c) return;
    int bn = blockIdx.x * 128;

    __shared__ float As[3][128 * 20];
    __shared__ float Bs[3][16 * 136];

    int tid = threadIdx.x;
    int ar = tid >> 1, ac = (tid & 1) * 8;
    const float* aRow = nullptr;
    if (gtok) {
        if (bm + ar < c) aRow = Az + (size_t)(gtok + z * T)[bm + ar] * K;
    } else {
        if (bm + ar < c) aRow = Az + (size_t)(bm + ar) * K;
    }
    bool aok = aRow != nullptr;
    int br = tid >> 4, bc = (tid & 15) * 8;
    const float* bPtr = Bz + (size_t)br * N + bn + bc;

    int warp = tid >> 5, lane = tid & 31;
    int wm = (warp >> 2) * 64, wn = (warp & 3) * 32;
    int lr = lane >> 2, lc = lane & 3;

    float acc[4][4][4] = {};

    auto stage = [&](int kb, int buf) {
        int ko = kb * 16;
        const float* as = aok ? aRow + ko + ac : Az;
        cp16(&As[buf][ar * 20 + ac],     as,                aok);
        cp16(&As[buf][ar * 20 + ac + 4], aok ? as + 4 : Az, aok);
        const float* bs = bPtr + (size_t)ko * N;
        cp16(&Bs[buf][br * 136 + bc],     bs,     true);
        cp16(&Bs[buf][br * 136 + bc + 4], bs + 4, true);
    };

    int nk = K >> 4;                       // >= 2 at all call sites
    stage(0, 0); cp_commit();
    stage(1, 1); cp_commit();

    for (int kb = 0; kb < nk; kb++) {
        if (kb + 1 < nk) cp_wait<1>(); else cp_wait<0>();
        __syncthreads();                   // single barrier per K-block
        int cur = kb % 3;
        #pragma unroll
        for (int k8 = 0; k8 < 2; k8++) {
            int kk = k8 * 8;
            uint32_t af[4][4], bf[4][2];
            #pragma unroll
            for (int mt = 0; mt < 4; mt++) {
                int r0 = wm + mt * 16 + lr;
                af[mt][0] = f2tf32(As[cur][r0 * 20 + kk + lc]);
                af[mt][1] = f2tf32(As[cur][(r0 + 8) * 20 + kk + lc]);
                af[mt][2] = f2tf32(As[cur][r0 * 20 + kk + lc + 4]);
                af[mt][3] = f2tf32(As[cur][(r0 + 8) * 20 + kk + lc + 4]);
            }
            #pragma unroll
            for (int nt = 0; nt < 4; nt++) {
                int cb = wn + nt * 8 + lr;
                bf[nt][0] = f2tf32(Bs[cur][(kk + lc) * 136 + cb]);
                bf[nt][1] = f2tf32(Bs[cur][(kk + lc + 4) * 136 + cb]);
            }
            #pragma unroll
            for (int mt = 0; mt < 4; mt++)
                #pragma unroll
                for (int nt = 0; nt < 4; nt++)
                    mma_tf32(acc[mt][nt], af[mt], bf[nt]);
        }
        if (kb + 2 < nk) { stage(kb + 2, (kb + 2) % 3); cp_commit(); }
    }

    #pragma unroll
    for (int mt = 0; mt < 4; mt++) {
        #pragma unroll
        for (int nt = 0; nt < 4; nt++) {
            int col = bn + wn + nt * 8 + 2 * lc;
            #pragma unroll
            for (int half = 0; half < 2; half++) {
                int r = bm + wm + mt * 16 + lr + half * 8;
                if (r >= c) continue;
                float v0 = acc[mt][nt][half * 2 + 0];
                float v1 = acc[mt][nt][half * 2 + 1];
                size_t idx = (size_t)r * N + col;
                if (mode == 1) {
                    v0 += add[idx]; v1 += add[idx + 1];
                } else if (mode == 3) {
                    float2 g = *(const float2*)&auxz[idx];
                    v0 *= g.x / (1.f + __expf(-g.x));
                    v1 *= g.y / (1.f + __expf(-g.y));
                }
                *(float2*)&Cz[idx] = make_float2(v0, v1);
            }
        }
    }
}

// ============ fused QKV projection + RoPE, one launch ==========================
// grid (12, 32): bn tiles 0-7 -> q (N=1024), 8-9 -> k, 10-11 -> v (N=256 each).
// Epilogue rotates (even,odd) column pairs = RoPE pairs for q,k.
__global__ __launch_bounds__(256, 2) void qkv_rope_kernel(
        const float* __restrict__ xn,
        const float* __restrict__ wq, const float* __restrict__ wk,
        const float* __restrict__ wv,
        float* __restrict__ q, float* __restrict__ k, float* __restrict__ v,
        const float* __restrict__ fcos, const float* __restrict__ fsin) {
    int bm = blockIdx.y * 128;
    int bn = blockIdx.x * 128;
    const float* Bsel; float* Cout; int Nl, bnn; bool dorope;
    if (bn < 1024)      { Bsel = wq; Cout = q; Nl = 1024; bnn = bn;        dorope = true;  }
    else if (bn < 1280) { Bsel = wk; Cout = k; Nl = 256;  bnn = bn - 1024; dorope = true;  }
    else                { Bsel = wv; Cout = v; Nl = 256;  bnn = bn - 1280; dorope = false; }

    __shared__ float As[3][128 * 20];
    __shared__ float Bs[3][16 * 136];

    int tid = threadIdx.x;
    int ar = tid >> 1, ac = (tid & 1) * 8;
    const float* aRow = xn + (size_t)(bm + ar) * D;
    int br = tid >> 4, bc = (tid & 15) * 8;
    const float* bPtr = Bsel + (size_t)br * Nl + bnn + bc;

    int warp = tid >> 5, lane = tid & 31;
    int wm = (warp >> 2) * 64, wn = (warp & 3) * 32;
    int lr = lane >> 2, lc = lane & 3;

    float acc[4][4][4] = {};

    auto stage = [&](int kb, int buf) {
        int ko = kb * 16;
        const float* as = aRow + ko + ac;
        cp16(&As[buf][ar * 20 + ac],     as,     true);
        cp16(&As[buf][ar * 20 + ac + 4], as + 4, true);
        const float* bs = bPtr + (size_t)ko * Nl;
        cp16(&Bs[buf][br * 136 + bc],     bs,     true);
        cp16(&Bs[buf][br * 136 + bc + 4], bs + 4, true);
    };

    constexpr int nk = D / 16;             // 64
    stage(0, 0); cp_commit();
    stage(1, 1); cp_commit();

    for (int kb = 0; kb < nk; kb++) {
        if (kb + 1 < nk) cp_wait<1>(); else cp_wait<0>();
        __syncthreads();
        int cur = kb % 3;
        #pragma unroll
        for (int k8 = 0; k8 < 2; k8++) {
            int kk = k8 * 8;
            uint32_t af[4][4], bf[4][2];
            #pragma unroll
            for (int mt = 0; mt < 4; mt++) {
                int r0 = wm + mt * 16 + lr;
                af[mt][0] = f2tf32(As[cur][r0 * 20 + kk + lc]);
                af[mt][1] = f2tf32(As[cur][(r0 + 8) * 20 + kk + lc]);
                af[mt][2] = f2tf32(As[cur][r0 * 20 + kk + lc + 4]);
                af[mt][3] = f2tf32(As[cur][(r0 + 8) * 20 + kk + lc + 4]);
            }
            #pragma unroll
            for (int nt = 0; nt < 4; nt++) {
                int cb = wn + nt * 8 + lr;
                bf[nt][0] = f2tf32(Bs[cur][(kk + lc) * 136 + cb]);
                bf[nt][1] = f2tf32(Bs[cur][(kk + lc + 4) * 136 + cb]);
            }
            #pragma unroll
            for (int mt = 0; mt < 4; mt++)
                #pragma unroll
                for (int nt = 0; nt < 4; nt++)
                    mma_tf32(acc[mt][nt], af[mt], bf[nt]);
        }
        if (kb + 2 < nk) { stage(kb + 2, (kb + 2) % 3); cp_commit(); }
    }

    #pragma unroll
    for (int mt = 0; mt < 4; mt++) {
        #pragma unroll
        for (int nt = 0; nt < 4; nt++) {
            int col = bnn + wn + nt * 8 + 2 * lc;     // even
            int i = (col & 63) >> 1;
            #pragma unroll
            for (int half = 0; half < 2; half++) {
                int r = bm + wm + mt * 16 + lr + half * 8;
                float v0 = acc[mt][nt][half * 2 + 0];
                float v1 = acc[mt][nt][half * 2 + 1];
                if (dorope) {
                    int s = r & (S - 1);
                    float cs = fcos[s * 32 + i], sn = fsin[s * 32 + i];
                    float t0 = v0 * cs - v1 * sn;
                    v1 = v0 * sn + v1 * cs;
                    v0 = t0;
                }
                *(float2*)&Cout[(size_t)r * Nl + col] = make_float2(v0, v1);
            }
        }
    }
}

// ============ tensor-core flash attention (causal, GQA, tf32 MMA) =============
// 128 threads = 4 warps, 16 q-rows each. P tile aliases the Q tile (Q is
// register-resident after fragment extraction). No max-tracking (scores bounded).
__global__ __launch_bounds__(128) void attn_mma_kernel(const float* __restrict__ q,
        const float* __restrict__ k, const float* __restrict__ v,
        float* __restrict__ o) {
    extern __shared__ float sm[];
    float* Qs = sm;                       // 64 x 68  (aliased by Ps after frags)
    float* Ps = sm;
    float* Ks = Qs + 64 * 68;             // 2 x 64 x 68
    float* Vs = Ks + 2 * 64 * 68;         // 2 x 64 x 72
    const int qt = gridDim.x - 1 - blockIdx.x;   // long blocks first
    const int h = blockIdx.y, b = blockIdx.z;
    const int kh = h / NREP;
    const int tid = threadIdx.x;
    const int warp = tid >> 5, lane = tid & 31;
    const int lr = lane >> 2, lc = lane & 3;
    const int wm = warp * 16;

    const float* kvrow = k + ((size_t)(b * S) * KH + kh) * HD;
    const float* vvrow = v + ((size_t)(b * S) * KH + kh) * HD;

    auto stageKV = [&](int kt, int buf) {
        float* Kd = Ks + buf * 64 * 68;
        float* Vd = Vs + buf * 64 * 72;
        #pragma unroll
        for (int j = 0; j < 8; j++) {                 // full 64x64 tiles
            int idx = tid + j * 128;
            int row = idx >> 4, c4 = (idx & 15) * 4;
            size_t go = (size_t)(kt * 64 + row) * (KH * HD) + c4;
            cp16(&Kd[row * 68 + c4], kvrow + go, true);
            cp16(&Vd[row * 72 + c4], vvrow + go, true);
        }
    };
    stageKV(0, 0);
    cp_commit();

    // stage Q, extract register fragments (reused across all kt)
    #pragma unroll
    for (int j = 0; j < 8; j++) {
        int idx = tid + j * 128;
        int row = idx >> 4, c4 = (idx & 15) * 4;
        *(float4*)&Qs[row * 68 + c4] =
            *(const float4*)&q[(size_t)(b * S + qt * 64 + row) * (H * HD) + h * HD + c4];
    }
    __syncthreads();
    uint32_t qf[8][4];
    #pragma unroll
    for (int ks = 0; ks < 8; ks++) {
        int r0 = wm + lr, cc = ks * 8 + lc;
        qf[ks][0] = __float_as_uint(Qs[r0 * 68 + cc]);
        qf[ks][1] = __float_as_uint(Qs[(r0 + 8) * 68 + cc]);
        qf[ks][2] = __float_as_uint(Qs[r0 * 68 + cc + 4]);
        qf[ks][3] = __float_as_uint(Qs[(r0 + 8) * 68 + cc + 4]);
    }

    float of[8][4] = {};
    float l0 = 0.f, l1 = 0.f;

    for (int kt = 0; kt <= qt; kt++) {
        int cur = kt & 1;
        if (kt < qt) { stageKV(kt + 1, cur ^ 1); cp_commit(); cp_wait<1>(); }
        else         { cp_wait<0>(); }
        __syncthreads();
        const float* Kc = Ks + cur * 64 * 68;
        const float* Vc = Vs + cur * 64 * 72;

        // S = Q @ K^T
        float sacc[8][4] = {};
        #pragma unroll
        for (int ks = 0; ks < 8; ks++) {
            #pragma unroll
            for (int nt = 0; nt < 8; nt++) {
                uint32_t bf[2];
                bf[0] = __float_as_uint(Kc[(nt * 8 + lr) * 68 + ks * 8 + lc]);
                bf[1] = __float_as_uint(Kc[(nt * 8 + lr) * 68 + ks * 8 + lc + 4]);
                mma_tf32(sacc[nt], qf[ks], bf);
            }
        }
        // P = exp(S/8) with causal mask on diagonal tile; accumulate row sums
        bool diag = (kt == qt);
        float ls0 = 0.f, ls1 = 0.f;
        #pragma unroll
        for (int nt = 0; nt < 8; nt++) {
            int c0 = nt * 8 + 2 * lc;
            int r0 = wm + lr, r1 = r0 + 8;
            float p00 = (diag && (c0     > r0)) ? 0.f : __expf(sacc[nt][0] * 0.125f);
            float p01 = (diag && (c0 + 1 > r0)) ? 0.f : __expf(sacc[nt][1] * 0.125f);
            float p10 = (diag && (c0     > r1)) ? 0.f : __expf(sacc[nt][2] * 0.125f);
            float p11 = (diag && (c0 + 1 > r1)) ? 0.f : __expf(sacc[nt][3] * 0.125f);
            ls0 += p00 + p01; ls1 += p10 + p11;
            *(float2*)&Ps[r0 * 68 + c0] = make_float2(p00, p01);
            *(float2*)&Ps[r1 * 68 + c0] = make_float2(p10, p11);
        }
        ls0 += __shfl_xor_sync(0xffffffffu, ls0, 1);
        ls0 += __shfl_xor_sync(0xffffffffu, ls0, 2);
        ls1 += __shfl_xor_sync(0xffffffffu, ls1, 1);
        ls1 += __shfl_xor_sync(0xffffffffu, ls1, 2);
        l0 += ls0; l1 += ls1;
        __syncwarp();    // Ps rows are warp-private

        // O += P @ V
        #pragma unroll
        for (int ks = 0; ks < 8; ks++) {
            uint32_t af[4];
            int r0 = wm + lr, cc = ks * 8 + lc;
            af[0] = __float_as_uint(Ps[r0 * 68 + cc]);
            af[1] = __float_as_uint(Ps[(r0 + 8) * 68 + cc]);
            af[2] = __float_as_uint(Ps[r0 * 68 + cc + 4]);
            af[3] = __float_as_uint(Ps[(r0 + 8) * 68 + cc + 4]);
            #pragma unroll
            for (int nt = 0; nt < 8; nt++) {
                uint32_t bf[2];
                bf[0] = __float_as_uint(Vc[(ks * 8 + lc) * 72 + nt * 8 + lr]);
                bf[1] = __float_as_uint(Vc[(ks * 8 + lc + 4) * 72 + nt * 8 + lr]);
                mma_tf32(of[nt], af, bf);
            }
        }
        __syncthreads();
    }

    float i0 = 1.f / l0, i1 = 1.f / l1;
    size_t o0 = (size_t)(b * S + qt * 64 + wm + lr) * (H * HD) + h * HD;
    #pragma unroll
    for (int nt = 0; nt < 8; nt++) {
        int c0 = nt * 8 + 2 * lc;
        *(float2*)&o[o0 + c0] = make_float2(of[nt][0] * i0, of[nt][1] * i0);
        *(float2*)&o[o0 + (size_t)8 * (H * HD) + c0] = make_float2(of[nt][2] * i1, of[nt][3] * i1);
    }
}

// ---------------- router: top-2 of softmax(hn @ gate_w), records slots --------
__global__ __launch_bounds__(256) void router_kernel(const float* __restrict__ hn,
        const float* __restrict__ gw, int* __restrict__ cnt,
        int* __restrict__ tok, float* __restrict__ wt, int* __restrict__ slot) {
    int t = blockIdx.x;
    int warp = threadIdx.x >> 5, lane = threadIdx.x & 31;
    const float* hr = hn + (size_t)t * D;
    float s = 0.f;
    for (int i = lane; i < D; i += 32) s += hr[i] * gw[i * E + warp];
    #pragma unroll
    for (int o = 16; o > 0; o >>= 1) s += __shfl_xor_sync(0xffffffffu, s, o);
    __shared__ float lg[E];
    if (lane == 0) lg[warp] = s;
    __syncthreads();
    if (threadIdx.x == 0) {
        int i0 = 0;
        for (int i = 1; i < E; i++) if (lg[i] > lg[i0]) i0 = i;
        int i1 = (i0 == 0) ? 1 : 0;
        for (int i = 0; i < E; i++) { if (i == i0) continue; if (lg[i] > lg[i1]) i1 = i; }
        float e1 = expf(lg[i1] - lg[i0]);
        float w0 = 1.f / (1.f + e1);
        float w1 = e1 * w0;
        int p0 = atomicAdd(&cnt[i0], 1);
        tok[i0 * T + p0] = t; wt[i0 * T + p0] = w0;
        int p1 = atomicAdd(&cnt[i1], 1);
        tok[i1 * T + p1] = t; wt[i1 * T + p1] = w1;
        slot[t * 2]     = i0 * T + p0;
        slot[t * 2 + 1] = i1 * T + p1;
    }
}

__global__ void zero_cnt_kernel(int* cnt) { if (threadIdx.x < E) cnt[threadIdx.x] = 0; }

// ---------------- final combine: out = h + w0*buf[s0] + w1*buf[s1] ------------
__global__ __launch_bounds__(256) void moe_combine_kernel(const float* __restrict__ h,
        const float* __restrict__ buf, const int* __restrict__ slot,
        const float* __restrict__ wt, float* __restrict__ out) {
    int t = blockIdx.x;
    int s0 = slot[t * 2], s1 = slot[t * 2 + 1];
    float w0 = wt[s0], w1 = wt[s1];
    const float4* h4 = (const float4*)(h + (size_t)t * D);
    const float4* b0 = (const float4*)(buf + (size_t)s0 * D);
    const float4* b1 = (const float4*)(buf + (size_t)s1 * D);
    float4* o4 = (float4*)(out + (size_t)t * D);
    int i = threadIdx.x;
    float4 hv = h4[i], v0 = b0[i], v1 = b1[i];
    o4[i] = make_float4(hv.x + w0 * v0.x + w1 * v1.x,
                        hv.y + w0 * v0.y + w1 * v1.y,
                        hv.z + w0 * v0.z + w1 * v1.z,
                        hv.w + w0 * v0.w + w1 * v1.w);
}

// ------------------------------- launch -------------------------------------
extern "C" void kernel_launch(void* const* d_in, const int* in_sizes, int n_in,
                              void* d_out, int out_size) {
    const float* x    = (const float*)d_in[0];
    const float* fcos = (const float*)d_in[3];
    const float* fsin = (const float*)d_in[4];
    const float* anw  = (const float*)d_in[5];
    const float* fnw  = (const float*)d_in[6];
    const float* wq   = (const float*)d_in[7];
    const float* wk   = (const float*)d_in[8];
    const float* wv   = (const float*)d_in[9];
    const float* wo   = (const float*)d_in[10];
    const float* gw   = (const float*)d_in[11];
    const float* w1   = (const float*)d_in[12];
    const float* w2   = (const float*)d_in[13];
    const float* w3   = (const float*)d_in[14];
    float* out = (float*)d_out;

    float *xn, *q, *k, *v, *at, *h, *hn, *act1, *act, *buf, *wt;
    int *cnt, *tok, *slot;
    cudaGetSymbolAddress((void**)&xn,   g_xn);
    cudaGetSymbolAddress((void**)&q,    g_q);
    cudaGetSymbolAddress((void**)&k,    g_k);
    cudaGetSymbolAddress((void**)&v,    g_v);
    cudaGetSymbolAddress((void**)&at,   g_at);
    cudaGetSymbolAddress((void**)&h,    g_h);
    cudaGetSymbolAddress((void**)&hn,   g_hn);
    cudaGetSymbolAddress((void**)&act1, g_act1);
    cudaGetSymbolAddress((void**)&act,  g_act);
    cudaGetSymbolAddress((void**)&buf,  g_buf);
    cudaGetSymbolAddress((void**)&cnt,  g_cnt);
    cudaGetSymbolAddress((void**)&tok,  g_tok);
    cudaGetSymbolAddress((void**)&wt,   g_wt);
    cudaGetSymbolAddress((void**)&slot, g_slot);

    const int ATTN_SMEM = (64 * 68 + 2 * 64 * 68 + 2 * 64 * 72) * (int)sizeof(float); // 89088
    cudaFuncSetAttribute(attn_mma_kernel, cudaFuncAttributeMaxDynamicSharedMemorySize, ATTN_SMEM);

    // 1) attn rmsnorm
    rmsnorm_kernel<<<T, 256>>>(x, anw, xn);
    // 2) fused QKV projection + RoPE
    qkv_rope_kernel<<<dim3(12, 32), 256>>>(xn, wq, wk, wv, q, k, v, fcos, fsin);
    // 3) causal flash attention (tensor cores)
    attn_mma_kernel<<<dim3(S / 64, H, B), 128, ATTN_SMEM>>>(q, k, v, at);
    // 4) output projection + residual: h = x + at @ wo
    gemm_tf32<<<dim3(8, 32, 1), 256>>>(at, wo, h, x, nullptr, nullptr, nullptr,
                                       T, D, H * HD, 1, 0, 0, 0);
    // 5) ffn rmsnorm
    rmsnorm_kernel<<<T, 256>>>(h, fnw, hn);
    // 6) routing
    zero_cnt_kernel<<<1, 32>>>(cnt);
    router_kernel<<<T, 256>>>(hn, gw, cnt, tok, wt, slot);
    // 7) expert FFNs batched over blockIdx.z
    gemm_tf32<<<dim3(HID / 128, T / 128, E), 256>>>(hn, w1, act1, nullptr, nullptr,
        tok, cnt, T, HID, D, 0, 0, (long long)D * HID, (long long)T * HID);
    gemm_tf32<<<dim3(HID / 128, T / 128, E), 256>>>(hn, w3, act, nullptr, act1,
        tok, cnt, T, HID, D, 3, 0, (long long)D * HID, (long long)T * HID);
    gemm_tf32<<<dim3(D / 128, T / 128, E), 256>>>(act, w2, buf, nullptr, nullptr,
        nullptr, cnt, T, D, HID, 0, (long long)T * HID, (long long)HID * D, (long long)T * D);
    // 8) out = h + w0*buf[slot0] + w1*buf[slot1]
    moe_combine_kernel<<<T, 256>>>(h, buf, slot, wt, out);
}